// round 10
// baseline (speedup 1.0000x reference)
#include <cuda_runtime.h>
#include <cuda_bf16.h>
#include <cstdint>

// ---------------------------------------------------------------------------
// CausalSelfAttentionSeparateHeads  (B=4, T=2048, C=1024, H=16, HS=64)
// Round 10: term-major MMA ordering (dependency distance 16/4), BK=64 GEMM.
// ---------------------------------------------------------------------------

#define BATCH 4
#define TLEN  2048
#define CDIM  1024
#define NHEAD 16
#define HSD   64
#define MROWS (BATCH*TLEN)   // 8192

// ----- scratch (device globals: allocation-free rule) -----
__device__ __nv_bfloat16 g_xhi[(size_t)MROWS*CDIM];
__device__ __nv_bfloat16 g_xlo[(size_t)MROWS*CDIM];
__device__ __nv_bfloat16 g_whi[(size_t)4*CDIM*CDIM];
__device__ __nv_bfloat16 g_wlo[(size_t)4*CDIM*CDIM];
__device__ __nv_bfloat16 g_qhi[(size_t)MROWS*HSD*NHEAD];
__device__ __nv_bfloat16 g_qlo[(size_t)MROWS*HSD*NHEAD];
__device__ __nv_bfloat16 g_khi[(size_t)MROWS*HSD*NHEAD];
__device__ __nv_bfloat16 g_klo[(size_t)MROWS*HSD*NHEAD];
__device__ __nv_bfloat16 g_vhi[(size_t)MROWS*HSD*NHEAD];
__device__ __nv_bfloat16 g_vlo[(size_t)MROWS*HSD*NHEAD];
__device__ __nv_bfloat16 g_yhi[(size_t)MROWS*CDIM];
__device__ __nv_bfloat16 g_ylo[(size_t)MROWS*CDIM];

static __device__ __forceinline__ uint32_t smem_u32(const void* p) {
    return (uint32_t)__cvta_generic_to_shared(p);
}
static __device__ __forceinline__ void split2(float x, float y, uint32_t& hi, uint32_t& lo) {
    __nv_bfloat16 hx = __float2bfloat16(x), hy = __float2bfloat16(y);
    hi = ((uint32_t)__bfloat16_as_ushort(hy) << 16) | (uint32_t)__bfloat16_as_ushort(hx);
    float rx = x - __bfloat162float(hx), ry = y - __bfloat162float(hy);
    asm("cvt.rn.bf16x2.f32 %0, %1, %2;" : "=r"(lo) : "f"(ry), "f"(rx));
}

#define MMA16816(c, a, b) \
    asm volatile("mma.sync.aligned.m16n8k16.row.col.f32.bf16.bf16.f32 " \
        "{%0,%1,%2,%3}, {%4,%5,%6,%7}, {%8,%9}, {%0,%1,%2,%3};" \
        : "+f"((c)[0]), "+f"((c)[1]), "+f"((c)[2]), "+f"((c)[3]) \
        : "r"((a)[0]), "r"((a)[1]), "r"((a)[2]), "r"((a)[3]), \
          "r"((b)[0]), "r"((b)[1]))

#define LDSM4(r, a) asm volatile("ldmatrix.sync.aligned.m8n8.x4.shared.b16 {%0,%1,%2,%3}, [%4];" \
    : "=r"((r)[0]), "=r"((r)[1]), "=r"((r)[2]), "=r"((r)[3]) : "r"(a))
#define LDSM4T(r, a) asm volatile("ldmatrix.sync.aligned.m8n8.x4.trans.shared.b16 {%0,%1,%2,%3}, [%4];" \
    : "=r"((r)[0]), "=r"((r)[1]), "=r"((r)[2]), "=r"((r)[3]) : "r"(a))

#define CPASYNC(dst, src) \
    asm volatile("cp.async.cg.shared.global [%0], [%1], 16;" :: "r"(dst), "l"(src) : "memory")
#define CP_COMMIT() asm volatile("cp.async.commit_group;" ::: "memory")
#define CP_WAIT1()  asm volatile("cp.async.wait_group 1;" ::: "memory")
#define CP_WAIT0()  asm volatile("cp.async.wait_group 0;" ::: "memory")

// ---------------------------------------------------------------------------
__global__ __launch_bounds__(256)
void split_kernel(const float* __restrict__ in, __nv_bfloat16* __restrict__ hi,
                  __nv_bfloat16* __restrict__ lo, int n) {
    int i = (blockIdx.x * 256 + threadIdx.x) * 4;
    if (i >= n) return;
    float4 v = *(const float4*)(in + i);
    uint32_t h0, l0, h1, l1;
    split2(v.x, v.y, h0, l0);
    split2(v.z, v.w, h1, l1);
    *(uint32_t*)(hi + i) = h0; *(uint32_t*)(hi + i + 2) = h1;
    *(uint32_t*)(lo + i) = l0; *(uint32_t*)(lo + i + 2) = l1;
}

// ---------------------------------------------------------------------------
// mma.sync GEMM, split-bf16, BK=64, 3-stage ring, term-major MMA order.
// MODE 1: fused QKV. MODE 0: out-proj, fp32 row-major.
// ---------------------------------------------------------------------------
#define BK     64
#define NCHK   (CDIM / BK)          // 16
#define RS2    144                  // bytes per smem row (128 data + 16 pad)
#define ARR_B  (128 * RS2)          // 18432
#define STG_B  (4 * ARR_B)          // 73728
#define NSTG   3
#define GEMM_SMEM (NSTG * STG_B)    // 221184

template<int MODE>
__global__ __launch_bounds__(256)
void mma_gemm(const __nv_bfloat16* __restrict__ Ahi, const __nv_bfloat16* __restrict__ Alo,
              const __nv_bfloat16* __restrict__ WhiB, const __nv_bfloat16* __restrict__ WloB,
              const float* __restrict__ b0, const float* __restrict__ b1,
              const float* __restrict__ b2, float* __restrict__ out,
              __nv_bfloat16* __restrict__ o0h, __nv_bfloat16* __restrict__ o0l,
              __nv_bfloat16* __restrict__ o1h, __nv_bfloat16* __restrict__ o1l,
              __nv_bfloat16* __restrict__ o2h, __nv_bfloat16* __restrict__ o2l) {
    extern __shared__ __align__(128) char smem[];
    const uint32_t sb = smem_u32(smem);
    const int tid = threadIdx.x, wid = tid >> 5, lane = tid & 31;
    const int wm = wid >> 2, wn = wid & 3;
    const int m0 = blockIdx.y * 128;

    int n0;
    const __nv_bfloat16 *Wh, *Wl;
    const float* bias;
    __nv_bfloat16 *ohi = nullptr, *olo = nullptr;
    if (MODE == 1) {
        const int gid = blockIdx.x >> 3;
        n0 = (blockIdx.x & 7) * 128;
        const size_t WSZ = (size_t)CDIM * CDIM;
        Wh = WhiB + (size_t)gid * WSZ;
        Wl = WloB + (size_t)gid * WSZ;
        bias = gid == 0 ? b0 : (gid == 1 ? b1 : b2);
        ohi  = gid == 0 ? o0h : (gid == 1 ? o1h : o2h);
        olo  = gid == 0 ? o0l : (gid == 1 ? o1l : o2l);
    } else {
        n0 = blockIdx.x * 128;
        Wh = WhiB; Wl = WloB; bias = b0;
    }

    // cp.async: each thread owns 2 (array,row) pairs, 8x16B chunks each
    const __nv_bfloat16* srcB[2];
    uint32_t dstB[2];
    #pragma unroll
    for (int j = 0; j < 2; j++) {
        int u = tid + 256 * j;
        int arr = u >> 7, row = u & 127;
        const __nv_bfloat16* bpt = (arr == 0) ? Ahi : (arr == 1) ? Alo : (arr == 2) ? Wh : Wl;
        srcB[j] = bpt + (size_t)(((arr < 2) ? m0 : n0) + row) * CDIM;
        dstB[j] = sb + arr * ARR_B + row * RS2;
    }

    float acc[4][4][4];
    #pragma unroll
    for (int mi = 0; mi < 4; mi++)
        #pragma unroll
        for (int ni = 0; ni < 4; ni++)
            #pragma unroll
            for (int e = 0; e < 4; e++) acc[mi][ni][e] = 0.f;

    // prologue: chunks 0,1 -> stages 0,1
    #pragma unroll
    for (int j = 0; j < 2; j++)
        #pragma unroll
        for (int cc = 0; cc < 8; cc++)
            CPASYNC(dstB[j] + cc * 16, srcB[j] + cc * 8);
    CP_COMMIT();
    #pragma unroll
    for (int j = 0; j < 2; j++)
        #pragma unroll
        for (int cc = 0; cc < 8; cc++)
            CPASYNC(dstB[j] + STG_B + cc * 16, srcB[j] + BK + cc * 8);
    CP_COMMIT();

    const uint32_t paOff = (uint32_t)((lane & 15) * RS2 + (lane >> 4) * 16);
    const uint32_t pbOff = (uint32_t)(((lane & 7) + ((lane >> 4) & 1) * 8) * RS2
                                      + ((lane >> 3) & 1) * 16);
    const uint32_t aBase0 = (uint32_t)(wm * 64) * RS2 + paOff;
    const uint32_t bBase0 = 2 * ARR_B + (uint32_t)(wn * 32) * RS2 + pbOff;

    for (int c = 0; c < NCHK; c++) {
        if (c < NCHK - 1) CP_WAIT1(); else CP_WAIT0();
        __syncthreads();
        if (c + 2 < NCHK) {
            const uint32_t so = (uint32_t)(((c + 2) % NSTG) * STG_B);
            const int koff = (c + 2) * BK;
            #pragma unroll
            for (int j = 0; j < 2; j++)
                #pragma unroll
                for (int cc = 0; cc < 8; cc++)
                    CPASYNC(dstB[j] + so + cc * 16, srcB[j] + koff + cc * 8);
            CP_COMMIT();
        }
        const uint32_t st = sb + (uint32_t)((c % NSTG) * STG_B);
        #pragma unroll
        for (int ks = 0; ks < 4; ks++) {
            uint32_t ah[4][4], al[4][4], bh[4][2], bl[4][2];
            const uint32_t aAddr = st + aBase0 + ks * 32;
            #pragma unroll
            for (int mi = 0; mi < 4; mi++) {
                LDSM4(ah[mi], aAddr + mi * 16 * RS2);
                LDSM4(al[mi], aAddr + ARR_B + mi * 16 * RS2);
            }
            const uint32_t bAddr = st + bBase0 + ks * 32;
            #pragma unroll
            for (int np = 0; np < 2; np++) {
                uint32_t bt[4];
                LDSM4(bt, bAddr + np * 16 * RS2);
                bh[2*np][0] = bt[0]; bh[2*np][1] = bt[1];
                bh[2*np+1][0] = bt[2]; bh[2*np+1][1] = bt[3];
                LDSM4(bt, bAddr + ARR_B + np * 16 * RS2);
                bl[2*np][0] = bt[0]; bl[2*np][1] = bt[1];
                bl[2*np+1][0] = bt[2]; bl[2*np+1][1] = bt[3];
            }
            // term-major: same-accumulator dependency distance = 16
            #pragma unroll
            for (int mi = 0; mi < 4; mi++)
                #pragma unroll
                for (int ni = 0; ni < 4; ni++)
                    MMA16816(acc[mi][ni], ah[mi], bh[ni]);
            #pragma unroll
            for (int mi = 0; mi < 4; mi++)
                #pragma unroll
                for (int ni = 0; ni < 4; ni++)
                    MMA16816(acc[mi][ni], ah[mi], bl[ni]);
            #pragma unroll
            for (int mi = 0; mi < 4; mi++)
                #pragma unroll
                for (int ni = 0; ni < 4; ni++)
                    MMA16816(acc[mi][ni], al[mi], bh[ni]);
        }
    }

    // epilogue
    const int g = lane >> 2, tq = lane & 3;
    #pragma unroll
    for (int mi = 0; mi < 4; mi++) {
        const int mA = m0 + wm * 64 + mi * 16 + g;
        #pragma unroll
        for (int ni = 0; ni < 4; ni++) {
            const int n = n0 + wn * 32 + ni * 8 + tq * 2;
            const float bx = bias[n], by = bias[n + 1];
            const float o0x = acc[mi][ni][0] + bx, o0y = acc[mi][ni][1] + by;
            const float o1x = acc[mi][ni][2] + bx, o1y = acc[mi][ni][3] + by;
            if (MODE == 0) {
                *(float2*)(out + (size_t)mA * CDIM + n)       = make_float2(o0x, o0y);
                *(float2*)(out + (size_t)(mA + 8) * CDIM + n) = make_float2(o1x, o1y);
            } else {
                const int h = n >> 6, d = n & (HSD - 1);
                uint32_t hh, ll;
                {
                    const int bi = mA >> 11, t0 = mA & (TLEN - 1);
                    const size_t i0 = ((size_t)(bi * NHEAD + h) * TLEN + t0) * HSD + d;
                    split2(o0x, o0y, hh, ll);
                    *(uint32_t*)(ohi + i0) = hh; *(uint32_t*)(olo + i0) = ll;
                }
                {
                    const int mB = mA + 8;
                    const int bi = mB >> 11, t1 = mB & (TLEN - 1);
                    const size_t i1 = ((size_t)(bi * NHEAD + h) * TLEN + t1) * HSD + d;
                    split2(o1x, o1y, hh, ll);
                    *(uint32_t*)(ohi + i1) = hh; *(uint32_t*)(olo + i1) = ll;
                }
            }
        }
    }
}

// ---------------------------------------------------------------------------
// Flash attention, split-bf16 mma.sync, 3-stage KV ring, term-interleaved MMAs.
// ---------------------------------------------------------------------------
#define AT_RS2   144
#define KV_ARR_B (64 * AT_RS2)
#define KV_STG_B (4 * KV_ARR_B)
#define Q_ARR_B  (128 * AT_RS2)
#define ATT_SMEM (3 * KV_STG_B + 2 * Q_ARR_B)  // 147456

__global__ __launch_bounds__(256)
void attn_mma(const __nv_bfloat16* __restrict__ qhg, const __nv_bfloat16* __restrict__ qlg,
              const __nv_bfloat16* __restrict__ khg, const __nv_bfloat16* __restrict__ klg,
              const __nv_bfloat16* __restrict__ vhg, const __nv_bfloat16* __restrict__ vlg,
              __nv_bfloat16* __restrict__ yhg, __nv_bfloat16* __restrict__ ylg) {
    extern __shared__ __align__(128) char smem[];
    const uint32_t sb = smem_u32(smem);
    const int tid = threadIdx.x, wid = tid >> 5, lane = tid & 31;
    const int g = lane >> 2, tq = lane & 3;
    const int bh = blockIdx.y, qb = blockIdx.x, q0 = qb * 128;
    const size_t base = (size_t)bh * TLEN * HSD;
    const uint32_t QOFF = 3 * KV_STG_B;
    const int nkb = 2 * qb + 2;

    const __nv_bfloat16* kvsrc[8];
    uint32_t kvdst[8];
    #pragma unroll
    for (int i = 0; i < 8; i++) {
        int v = tid + 256 * i;
        int arr = v >> 9, w = v & 511, row = w >> 3, cc = w & 7;
        const __nv_bfloat16* bp = arr == 0 ? khg : arr == 1 ? klg : arr == 2 ? vhg : vlg;
        kvsrc[i] = bp + base + row * HSD + cc * 8;
        kvdst[i] = sb + arr * KV_ARR_B + row * AT_RS2 + cc * 16;
    }
    #pragma unroll
    for (int i = 0; i < 8; i++) {
        int v = tid + 256 * i;
        int arr = v >> 10, w = v & 1023, row = w >> 3, cc = w & 7;
        const __nv_bfloat16* src = (arr ? qlg : qhg) + base + (size_t)(q0 + row) * HSD + cc * 8;
        CPASYNC(sb + QOFF + arr * Q_ARR_B + row * AT_RS2 + cc * 16, src);
    }
    #pragma unroll
    for (int i = 0; i < 8; i++) CPASYNC(kvdst[i], kvsrc[i]);
    CP_COMMIT();
    #pragma unroll
    for (int i = 0; i < 8; i++) CPASYNC(kvdst[i] + KV_STG_B, kvsrc[i] + 64 * HSD);
    CP_COMMIT();

    const uint32_t paOff = (uint32_t)((lane & 15) * AT_RS2 + (lane >> 4) * 16);
    const uint32_t pbOff = (uint32_t)(((lane & 7) + ((lane >> 4) & 1) * 8) * AT_RS2
                                      + ((lane >> 3) & 1) * 16);

    uint32_t qh[4][4], ql[4][4];
    float m0 = -1e30f, m1 = -1e30f, l0 = 0.f, l1 = 0.f;
    float acc[8][4];
    #pragma unroll
    for (int df = 0; df < 8; df++)
        #pragma unroll
        for (int e = 0; e < 4; e++) acc[df][e] = 0.f;

    const int row0 = q0 + wid * 16 + g, row1 = row0 + 8;

    for (int kb = 0; kb < nkb; kb++) {
        if (kb < nkb - 1) CP_WAIT1(); else CP_WAIT0();
        __syncthreads();
        if (kb + 2 < nkb) {
            const uint32_t so = (uint32_t)(((kb + 2) % 3) * KV_STG_B);
            const size_t ko = (size_t)(kb + 2) * 64 * HSD;
            #pragma unroll
            for (int i = 0; i < 8; i++) CPASYNC(kvdst[i] + so, kvsrc[i] + ko);
            CP_COMMIT();
        }
        if (kb == 0) {
            const uint32_t qbse = sb + QOFF + (uint32_t)(wid * 16) * AT_RS2 + paOff;
            #pragma unroll
            for (int kk = 0; kk < 4; kk++) {
                LDSM4(qh[kk], qbse + kk * 32);
                LDSM4(ql[kk], qbse + Q_ARR_B + kk * 32);
            }
        }

        const uint32_t stg = sb + (uint32_t)((kb % 3) * KV_STG_B);

        // ---- S = Q K^T (term-interleaved pairs: dep distance 4)
        float sf[8][4];
        #pragma unroll
        for (int jf = 0; jf < 8; jf++)
            #pragma unroll
            for (int e = 0; e < 4; e++) sf[jf][e] = 0.f;

        const uint32_t kBase = stg + pbOff;
        #pragma unroll
        for (int kk = 0; kk < 4; kk++)
            #pragma unroll
            for (int jp2 = 0; jp2 < 4; jp2 += 2) {
                uint32_t kh4[2][4], kl4[2][4];
                #pragma unroll
                for (int p = 0; p < 2; p++) {
                    LDSM4(kh4[p], kBase + (jp2 + p) * (16 * AT_RS2) + kk * 32);
                    LDSM4(kl4[p], kBase + KV_ARR_B + (jp2 + p) * (16 * AT_RS2) + kk * 32);
                }
                #pragma unroll
                for (int p = 0; p < 2; p++) {
                    MMA16816(sf[2*(jp2+p)],   qh[kk], &kh4[p][0]);
                    MMA16816(sf[2*(jp2+p)+1], qh[kk], &kh4[p][2]);
                }
                #pragma unroll
                for (int p = 0; p < 2; p++) {
                    MMA16816(sf[2*(jp2+p)],   qh[kk], &kl4[p][0]);
                    MMA16816(sf[2*(jp2+p)+1], qh[kk], &kl4[p][2]);
                }
                #pragma unroll
                for (int p = 0; p < 2; p++) {
                    MMA16816(sf[2*(jp2+p)],   ql[kk], &kh4[p][0]);
                    MMA16816(sf[2*(jp2+p)+1], ql[kk], &kh4[p][2]);
                }
            }

        // ---- scale + causal mask
        const int k0 = kb * 64;
        const bool diag = (k0 + 63 > q0);
        #pragma unroll
        for (int jf = 0; jf < 8; jf++) {
            const int cb = k0 + 8 * jf + 2 * tq;
            sf[jf][0] *= 0.125f; sf[jf][1] *= 0.125f;
            sf[jf][2] *= 0.125f; sf[jf][3] *= 0.125f;
            if (diag) {
                if (cb     > row0) sf[jf][0] = -1e30f;
                if (cb + 1 > row0) sf[jf][1] = -1e30f;
                if (cb     > row1) sf[jf][2] = -1e30f;
                if (cb + 1 > row1) sf[jf][3] = -1e30f;
            }
        }

        // ---- online softmax
        float mx0 = -1e30f, mx1 = -1e30f;
        #pragma unroll
        for (int jf = 0; jf < 8; jf++) {
            mx0 = fmaxf(mx0, fmaxf(sf[jf][0], sf[jf][1]));
            mx1 = fmaxf(mx1, fmaxf(sf[jf][2], sf[jf][3]));
        }
        mx0 = fmaxf(mx0, __shfl_xor_sync(0xffffffffu, mx0, 1));
        mx0 = fmaxf(mx0, __shfl_xor_sync(0xffffffffu, mx0, 2));
        mx1 = fmaxf(mx1, __shfl_xor_sync(0xffffffffu, mx1, 1));
        mx1 = fmaxf(mx1, __shfl_xor_sync(0xffffffffu, mx1, 2));
        const float mn0 = fmaxf(m0, mx0), mn1 = fmaxf(m1, mx1);
        const float al0 = __expf(m0 - mn0), al1 = __expf(m1 - mn1);
        float rs0 = 0.f, rs1 = 0.f;
        #pragma unroll
        for (int jf = 0; jf < 8; jf++) {
            sf[jf][0] = __expf(sf[jf][0] - mn0);
            sf[jf][1] = __expf(sf[jf][1] - mn0);
            sf[jf][2] = __expf(sf[jf][2] - mn1);
            sf[jf][3] = __expf(sf[jf][3] - mn1);
            rs0 += sf[jf][0] + sf[jf][1];
            rs1 += sf[jf][2] + sf[jf][3];
        }
        rs0 += __shfl_xor_sync(0xffffffffu, rs0, 1);
        rs0 += __shfl_xor_sync(0xffffffffu, rs0, 2);
        rs1 += __shfl_xor_sync(0xffffffffu, rs1, 1);
        rs1 += __shfl_xor_sync(0xffffffffu, rs1, 2);
        l0 = l0 * al0 + rs0; l1 = l1 * al1 + rs1;
        m0 = mn0; m1 = mn1;
        #pragma unroll
        for (int df = 0; df < 8; df++) {
            acc[df][0] *= al0; acc[df][1] *= al0;
            acc[df][2] *= al1; acc[df][3] *= al1;
        }

        // ---- O += P V (term-interleaved pairs: dep distance 4)
        const uint32_t vBase = stg + 2 * KV_ARR_B + paOff;
        #pragma unroll
        for (int jp = 0; jp < 4; jp++) {
            uint32_t ah4[4], al4[4];
            split2(sf[2 * jp][0],     sf[2 * jp][1],     ah4[0], al4[0]);
            split2(sf[2 * jp][2],     sf[2 * jp][3],     ah4[1], al4[1]);
            split2(sf[2 * jp + 1][0], sf[2 * jp + 1][1], ah4[2], al4[2]);
            split2(sf[2 * jp + 1][2], sf[2 * jp + 1][3], ah4[3], al4[3]);
            #pragma unroll
            for (int dp2 = 0; dp2 < 4; dp2 += 2) {
                uint32_t vh4[2][4], vl4[2][4];
                #pragma unroll
                for (int p = 0; p < 2; p++) {
                    LDSM4T(vh4[p], vBase + jp * (16 * AT_RS2) + (dp2 + p) * 32);
                    LDSM4T(vl4[p], vBase + KV_ARR_B + jp * (16 * AT_RS2) + (dp2 + p) * 32);
                }
                #pragma unroll
                for (int p = 0; p < 2; p++) {
                    MMA16816(acc[2*(dp2+p)],   ah4, &vh4[p][0]);
                    MMA16816(acc[2*(dp2+p)+1], ah4, &vh4[p][2]);
                }
                #pragma unroll
                for (int p = 0; p < 2; p++) {
                    MMA16816(acc[2*(dp2+p)],   ah4, &vl4[p][0]);
                    MMA16816(acc[2*(dp2+p)+1], ah4, &vl4[p][2]);
                }
                #pragma unroll
                for (int p = 0; p < 2; p++) {
                    MMA16816(acc[2*(dp2+p)],   al4, &vh4[p][0]);
                    MMA16816(acc[2*(dp2+p)+1], al4, &vh4[p][2]);
                }
            }
        }
    }

    // ---- epilogue
    const int b = bh >> 4, h = bh & 15;
    const float i0 = 1.f / l0, i1 = 1.f / l1;
    #pragma unroll
    for (int df = 0; df < 8; df++) {
        const int col = h * HSD + 8 * df + 2 * tq;
        uint32_t hh, ll;
        split2(acc[df][0] * i0, acc[df][1] * i0, hh, ll);
        const size_t idx0 = ((size_t)(b * TLEN + row0)) * CDIM + col;
        *(uint32_t*)(yhg + idx0) = hh; *(uint32_t*)(ylg + idx0) = ll;
        split2(acc[df][2] * i1, acc[df][3] * i1, hh, ll);
        const size_t idx1 = ((size_t)(b * TLEN + row1)) * CDIM + col;
        *(uint32_t*)(yhg + idx1) = hh; *(uint32_t*)(ylg + idx1) = ll;
    }
}

// ---------------------------------------------------------------------------
extern "C" void kernel_launch(void* const* d_in, const int* in_sizes, int n_in,
                              void* d_out, int out_size) {
    const float* x  = (const float*)d_in[0];
    const float* Wq = (const float*)d_in[1];
    const float* bq = (const float*)d_in[2];
    const float* Wk = (const float*)d_in[3];
    const float* bk = (const float*)d_in[4];
    const float* Wv = (const float*)d_in[5];
    const float* bv = (const float*)d_in[6];
    const float* Wp = (const float*)d_in[7];
    const float* bp = (const float*)d_in[8];
    float* out = (float*)d_out;

    __nv_bfloat16 *xhi, *xlo, *whi, *wlo, *qhi, *qlo, *khi, *klo, *vhi, *vlo, *yhi, *ylo;
    cudaGetSymbolAddress((void**)&xhi, g_xhi);
    cudaGetSymbolAddress((void**)&xlo, g_xlo);
    cudaGetSymbolAddress((void**)&whi, g_whi);
    cudaGetSymbolAddress((void**)&wlo, g_wlo);
    cudaGetSymbolAddress((void**)&qhi, g_qhi);
    cudaGetSymbolAddress((void**)&qlo, g_qlo);
    cudaGetSymbolAddress((void**)&khi, g_khi);
    cudaGetSymbolAddress((void**)&klo, g_klo);
    cudaGetSymbolAddress((void**)&vhi, g_vhi);
    cudaGetSymbolAddress((void**)&vlo, g_vlo);
    cudaGetSymbolAddress((void**)&yhi, g_yhi);
    cudaGetSymbolAddress((void**)&ylo, g_ylo);

    static bool attr_set = false;
    if (!attr_set) {
        cudaFuncSetAttribute(attn_mma,
                             cudaFuncAttributeMaxDynamicSharedMemorySize, ATT_SMEM);
        cudaFuncSetAttribute(mma_gemm<0>,
                             cudaFuncAttributeMaxDynamicSharedMemorySize, GEMM_SMEM);
        cudaFuncSetAttribute(mma_gemm<1>,
                             cudaFuncAttributeMaxDynamicSharedMemorySize, GEMM_SMEM);
        attr_set = true;
    }

    const size_t WSZ = (size_t)CDIM * CDIM;

    split_kernel<<<MROWS*CDIM/1024, 256>>>(x, xhi, xlo, MROWS*CDIM);
    split_kernel<<<WSZ/1024, 256>>>(Wq, whi + 0*WSZ, wlo + 0*WSZ, (int)WSZ);
    split_kernel<<<WSZ/1024, 256>>>(Wk, whi + 1*WSZ, wlo + 1*WSZ, (int)WSZ);
    split_kernel<<<WSZ/1024, 256>>>(Wv, whi + 2*WSZ, wlo + 2*WSZ, (int)WSZ);
    split_kernel<<<WSZ/1024, 256>>>(Wp, whi + 3*WSZ, wlo + 3*WSZ, (int)WSZ);

    mma_gemm<1><<<dim3(24, MROWS/128), 256, GEMM_SMEM>>>(
        xhi, xlo, whi, wlo, bq, bk, bv, nullptr,
        qhi, qlo, khi, klo, vhi, vlo);

    attn_mma<<<dim3(TLEN/128, BATCH*NHEAD), 256, ATT_SMEM>>>(qhi, qlo, khi, klo,
                                                             vhi, vlo, yhi, ylo);

    mma_gemm<0><<<dim3(CDIM/128, MROWS/128), 256, GEMM_SMEM>>>(
        yhi, ylo, whi + 3*WSZ, wlo + 3*WSZ, bp, nullptr, nullptr, out,
        nullptr, nullptr, nullptr, nullptr, nullptr, nullptr);
}

// round 11
// speedup vs baseline: 1.2185x; 1.2185x over previous
#include <cuda_runtime.h>
#include <cuda_bf16.h>
#include <cstdint>

// ---------------------------------------------------------------------------
// CausalSelfAttentionSeparateHeads  (B=4, T=2048, C=1024, H=16, HS=64)
// Round 11: round-8 architecture (proven 1182us) + forced 2-CTA/SM residency
//           via __launch_bounds__(256, 2) on GEMM and attention.
// ---------------------------------------------------------------------------

#define BATCH 4
#define TLEN  2048
#define CDIM  1024
#define NHEAD 16
#define HSD   64
#define MROWS (BATCH*TLEN)   // 8192

// ----- scratch (device globals: allocation-free rule) -----
__device__ __nv_bfloat16 g_xhi[(size_t)MROWS*CDIM];
__device__ __nv_bfloat16 g_xlo[(size_t)MROWS*CDIM];
__device__ __nv_bfloat16 g_whi[(size_t)4*CDIM*CDIM];
__device__ __nv_bfloat16 g_wlo[(size_t)4*CDIM*CDIM];
__device__ __nv_bfloat16 g_qhi[(size_t)MROWS*HSD*NHEAD];  // [bh][t][64]
__device__ __nv_bfloat16 g_qlo[(size_t)MROWS*HSD*NHEAD];
__device__ __nv_bfloat16 g_khi[(size_t)MROWS*HSD*NHEAD];
__device__ __nv_bfloat16 g_klo[(size_t)MROWS*HSD*NHEAD];
__device__ __nv_bfloat16 g_vhi[(size_t)MROWS*HSD*NHEAD];
__device__ __nv_bfloat16 g_vlo[(size_t)MROWS*HSD*NHEAD];
__device__ __nv_bfloat16 g_yhi[(size_t)MROWS*CDIM];       // [b][t][C]
__device__ __nv_bfloat16 g_ylo[(size_t)MROWS*CDIM];

static __device__ __forceinline__ uint32_t smem_u32(const void* p) {
    return (uint32_t)__cvta_generic_to_shared(p);
}
static __device__ __forceinline__ void split2(float x, float y, uint32_t& hi, uint32_t& lo) {
    __nv_bfloat16 hx = __float2bfloat16(x), hy = __float2bfloat16(y);
    hi = ((uint32_t)__bfloat16_as_ushort(hy) << 16) | (uint32_t)__bfloat16_as_ushort(hx);
    float rx = x - __bfloat162float(hx), ry = y - __bfloat162float(hy);
    asm("cvt.rn.bf16x2.f32 %0, %1, %2;" : "=r"(lo) : "f"(ry), "f"(rx));
}

#define MMA16816(c, a, b) \
    asm volatile("mma.sync.aligned.m16n8k16.row.col.f32.bf16.bf16.f32 " \
        "{%0,%1,%2,%3}, {%4,%5,%6,%7}, {%8,%9}, {%0,%1,%2,%3};" \
        : "+f"((c)[0]), "+f"((c)[1]), "+f"((c)[2]), "+f"((c)[3]) \
        : "r"((a)[0]), "r"((a)[1]), "r"((a)[2]), "r"((a)[3]), \
          "r"((b)[0]), "r"((b)[1]))

#define LDSM4(r, a) asm volatile("ldmatrix.sync.aligned.m8n8.x4.shared.b16 {%0,%1,%2,%3}, [%4];" \
    : "=r"((r)[0]), "=r"((r)[1]), "=r"((r)[2]), "=r"((r)[3]) : "r"(a))
#define LDSM4T(r, a) asm volatile("ldmatrix.sync.aligned.m8n8.x4.trans.shared.b16 {%0,%1,%2,%3}, [%4];" \
    : "=r"((r)[0]), "=r"((r)[1]), "=r"((r)[2]), "=r"((r)[3]) : "r"(a))

#define CPASYNC(dst, src) \
    asm volatile("cp.async.cg.shared.global [%0], [%1], 16;" :: "r"(dst), "l"(src) : "memory")
#define CP_COMMIT() asm volatile("cp.async.commit_group;" ::: "memory")
#define CP_WAIT1()  asm volatile("cp.async.wait_group 1;" ::: "memory")
#define CP_WAIT0()  asm volatile("cp.async.wait_group 0;" ::: "memory")

// ---------------------------------------------------------------------------
// split fp32 -> bf16 hi + bf16 lo
// ---------------------------------------------------------------------------
__global__ __launch_bounds__(256)
void split_kernel(const float* __restrict__ in, __nv_bfloat16* __restrict__ hi,
                  __nv_bfloat16* __restrict__ lo, int n) {
    int i = (blockIdx.x * 256 + threadIdx.x) * 4;
    if (i >= n) return;
    float4 v = *(const float4*)(in + i);
    uint32_t h0, l0, h1, l1;
    split2(v.x, v.y, h0, l0);
    split2(v.z, v.w, h1, l1);
    *(uint32_t*)(hi + i) = h0; *(uint32_t*)(hi + i + 2) = h1;
    *(uint32_t*)(lo + i) = l0; *(uint32_t*)(lo + i + 2) = l1;
}

// ---------------------------------------------------------------------------
// mma.sync GEMM (round-8 layout): out[m,n] = sum_k A[m,k]*W[n,k] + bias[n]
// BK=32, 2-stage cp.async, scalar LDS frags, 80 B row stride, 2 CTAs/SM.
// MODE 0: fp32 row-major out.  MODE 1: bf16 hi/lo scatter to [B,H,T,HS].
// ---------------------------------------------------------------------------
#define BK     32
#define NCHK   (CDIM / BK)          // 32
#define RSTRIDE 40
#define ARR_B  (128 * RSTRIDE * 2)  // 10240
#define STG_B  (4 * ARR_B)          // 40960
#define GEMM_SMEM (2 * STG_B)       // 81920  (x2 CTAs = 163840 <= 228KB)

template<int MODE>
__global__ __launch_bounds__(256, 2)
void mma_gemm(const __nv_bfloat16* __restrict__ Ahi, const __nv_bfloat16* __restrict__ Alo,
              const __nv_bfloat16* __restrict__ Whi, const __nv_bfloat16* __restrict__ Wlo,
              const float* __restrict__ bias, float* __restrict__ out,
              __nv_bfloat16* __restrict__ ohi, __nv_bfloat16* __restrict__ olo) {
    extern __shared__ __align__(128) char smem[];
    const uint32_t sb = smem_u32(smem);

    const int tid  = threadIdx.x;
    const int wid  = tid >> 5, lane = tid & 31;
    const int wm   = wid >> 2, wn   = wid & 3;
    const int g    = lane >> 2, tq  = lane & 3;
    const int m0   = blockIdx.y * 128, n0 = blockIdx.x * 128;

    const __nv_bfloat16* srcs[8];
    uint32_t dsts[8];
    #pragma unroll
    for (int i = 0; i < 8; i++) {
        int v = tid + 256 * i;
        int t = v >> 9, w = v & 511, row = w >> 2, cc = w & 3;
        const __nv_bfloat16* base = (t == 0) ? Ahi : (t == 1) ? Alo : (t == 2) ? Whi : Wlo;
        int grow = ((t < 2) ? m0 : n0) + row;
        srcs[i] = base + (size_t)grow * CDIM + cc * 8;
        dsts[i] = sb + t * ARR_B + row * (RSTRIDE * 2) + cc * 16;
    }

    float acc[4][4][4];
    #pragma unroll
    for (int mi = 0; mi < 4; mi++)
        #pragma unroll
        for (int ni = 0; ni < 4; ni++)
            #pragma unroll
            for (int e = 0; e < 4; e++) acc[mi][ni][e] = 0.f;

    #pragma unroll
    for (int i = 0; i < 8; i++) CPASYNC(dsts[i], srcs[i]);
    CP_COMMIT();

    const uint32_t aRow = (uint32_t)(wm * 64 + g) * (RSTRIDE * 2);
    const uint32_t bRow = (uint32_t)(wn * 32 + g) * (RSTRIDE * 2);
    const uint32_t kOff = (uint32_t)(tq * 2) * 2;

    for (int c = 0; c < NCHK; c++) {
        const int s = c & 1;
        if (c + 1 < NCHK) {
            const uint32_t so = (uint32_t)((s ^ 1) * STG_B);
            const int koff = (c + 1) * BK;
            #pragma unroll
            for (int i = 0; i < 8; i++) CPASYNC(dsts[i] + so, srcs[i] + koff);
            CP_COMMIT();
            CP_WAIT1();
        } else {
            CP_WAIT0();
        }
        __syncthreads();

        const char* st = smem + s * STG_B;
        #pragma unroll
        for (int ks = 0; ks < 2; ks++) {
            const uint32_t kb = kOff + ks * 32;
            uint32_t ah[4][4], al[4][4], bh[4][2], bl[4][2];
            #pragma unroll
            for (int mi = 0; mi < 4; mi++) {
                const char* p0 = st + 0 * ARR_B + aRow + mi * 16 * (RSTRIDE * 2) + kb;
                const char* p1 = st + 1 * ARR_B + aRow + mi * 16 * (RSTRIDE * 2) + kb;
                ah[mi][0] = *(const uint32_t*)(p0);
                ah[mi][1] = *(const uint32_t*)(p0 + 8 * (RSTRIDE * 2));
                ah[mi][2] = *(const uint32_t*)(p0 + 16);
                ah[mi][3] = *(const uint32_t*)(p0 + 8 * (RSTRIDE * 2) + 16);
                al[mi][0] = *(const uint32_t*)(p1);
                al[mi][1] = *(const uint32_t*)(p1 + 8 * (RSTRIDE * 2));
                al[mi][2] = *(const uint32_t*)(p1 + 16);
                al[mi][3] = *(const uint32_t*)(p1 + 8 * (RSTRIDE * 2) + 16);
            }
            #pragma unroll
            for (int ni = 0; ni < 4; ni++) {
                const char* p2 = st + 2 * ARR_B + bRow + ni * 8 * (RSTRIDE * 2) + kb;
                const char* p3 = st + 3 * ARR_B + bRow + ni * 8 * (RSTRIDE * 2) + kb;
                bh[ni][0] = *(const uint32_t*)(p2);
                bh[ni][1] = *(const uint32_t*)(p2 + 16);
                bl[ni][0] = *(const uint32_t*)(p3);
                bl[ni][1] = *(const uint32_t*)(p3 + 16);
            }
            #pragma unroll
            for (int mi = 0; mi < 4; mi++)
                #pragma unroll
                for (int ni = 0; ni < 4; ni++) {
                    MMA16816(acc[mi][ni], ah[mi], bh[ni]);
                    MMA16816(acc[mi][ni], ah[mi], bl[ni]);
                    MMA16816(acc[mi][ni], al[mi], bh[ni]);
                }
        }
        __syncthreads();
    }

    #pragma unroll
    for (int mi = 0; mi < 4; mi++) {
        const int mA = m0 + wm * 64 + mi * 16 + g;
        #pragma unroll
        for (int ni = 0; ni < 4; ni++) {
            const int n  = n0 + wn * 32 + ni * 8 + tq * 2;
            const float bx = bias[n], by = bias[n + 1];
            const float o0x = acc[mi][ni][0] + bx, o0y = acc[mi][ni][1] + by;
            const float o1x = acc[mi][ni][2] + bx, o1y = acc[mi][ni][3] + by;
            if (MODE == 0) {
                *(float2*)(out + (size_t)mA * CDIM + n)       = make_float2(o0x, o0y);
                *(float2*)(out + (size_t)(mA + 8) * CDIM + n) = make_float2(o1x, o1y);
            } else {
                const int h = n >> 6, d = n & (HSD - 1);
                uint32_t hh, ll;
                {
                    const int bi = mA >> 11, t0 = mA & (TLEN - 1);
                    const size_t i0 = ((size_t)(bi * NHEAD + h) * TLEN + t0) * HSD + d;
                    split2(o0x, o0y, hh, ll);
                    *(uint32_t*)(ohi + i0) = hh; *(uint32_t*)(olo + i0) = ll;
                }
                {
                    const int mB = mA + 8;
                    const int bi = mB >> 11, t1 = mB & (TLEN - 1);
                    const size_t i1 = ((size_t)(bi * NHEAD + h) * TLEN + t1) * HSD + d;
                    split2(o1x, o1y, hh, ll);
                    *(uint32_t*)(ohi + i1) = hh; *(uint32_t*)(olo + i1) = ll;
                }
            }
        }
    }
}

// ---------------------------------------------------------------------------
// Flash attention, split-bf16 mma.sync (round-8 layout), 2-stage KV ring,
// forced 2 CTAs/SM.
// ---------------------------------------------------------------------------
#define AT_RS2   144
#define KV_ARR_B (64 * AT_RS2)              // 9216
#define KV_STG_B (4 * KV_ARR_B)             // 36864
#define Q_ARR_B  (128 * AT_RS2)             // 18432
#define ATT_SMEM (2 * KV_STG_B + 2 * Q_ARR_B)  // 110592 (x2 CTAs = 221184)

__global__ __launch_bounds__(256, 2)
void attn_mma(const __nv_bfloat16* __restrict__ qhg, const __nv_bfloat16* __restrict__ qlg,
              const __nv_bfloat16* __restrict__ khg, const __nv_bfloat16* __restrict__ klg,
              const __nv_bfloat16* __restrict__ vhg, const __nv_bfloat16* __restrict__ vlg,
              __nv_bfloat16* __restrict__ yhg, __nv_bfloat16* __restrict__ ylg) {
    extern __shared__ __align__(128) char smem[];
    const uint32_t sb = smem_u32(smem);
    const int tid = threadIdx.x, wid = tid >> 5, lane = tid & 31;
    const int g = lane >> 2, tq = lane & 3;
    const int bh = blockIdx.y, qb = blockIdx.x, q0 = qb * 128;
    const size_t base = (size_t)bh * TLEN * HSD;
    const uint32_t QOFF = 2 * KV_STG_B;

    const __nv_bfloat16* kvsrc[8];
    uint32_t kvdst[8];
    #pragma unroll
    for (int i = 0; i < 8; i++) {
        int v = tid + 256 * i;
        int arr = v >> 9, w = v & 511, row = w >> 3, cc = w & 7;
        const __nv_bfloat16* bp = arr == 0 ? khg : arr == 1 ? klg : arr == 2 ? vhg : vlg;
        kvsrc[i] = bp + base + row * HSD + cc * 8;
        kvdst[i] = sb + arr * KV_ARR_B + row * AT_RS2 + cc * 16;
    }
    #pragma unroll
    for (int i = 0; i < 8; i++) {
        int v = tid + 256 * i;
        int arr = v >> 10, w = v & 1023, row = w >> 3, cc = w & 7;
        const __nv_bfloat16* src = (arr ? qlg : qhg) + base + (size_t)(q0 + row) * HSD + cc * 8;
        CPASYNC(sb + QOFF + arr * Q_ARR_B + row * AT_RS2 + cc * 16, src);
    }
    CP_COMMIT();
    #pragma unroll
    for (int i = 0; i < 8; i++) CPASYNC(kvdst[i], kvsrc[i]);
    CP_COMMIT();

    CP_WAIT1();
    __syncthreads();

    const uint32_t paOff = (uint32_t)(((lane & 7) + ((lane >> 3) & 1) * 8) * AT_RS2 + (lane >> 4) * 16);
    const uint32_t pbOff = (uint32_t)(((lane & 7) + ((lane >> 4) & 1) * 8) * AT_RS2 + ((lane >> 3) & 1) * 16);

    uint32_t qh[4][4], ql[4][4];
    {
        const uint32_t qbse = sb + QOFF + (uint32_t)(wid * 16) * AT_RS2 + paOff;
        #pragma unroll
        for (int kk = 0; kk < 4; kk++) {
            LDSM4(qh[kk], qbse + kk * 32);
            LDSM4(ql[kk], qbse + Q_ARR_B + kk * 32);
        }
    }

    float m0 = -1e30f, m1 = -1e30f, l0 = 0.f, l1 = 0.f;
    float acc[8][4];
    #pragma unroll
    for (int df = 0; df < 8; df++)
        #pragma unroll
        for (int e = 0; e < 4; e++) acc[df][e] = 0.f;

    const int nkb = 2 * qb + 2;
    const int row0 = q0 + wid * 16 + g, row1 = row0 + 8;

    for (int kb = 0; kb < nkb; kb++) {
        const int s = kb & 1;
        if (kb + 1 < nkb) {
            const uint32_t so = (uint32_t)((s ^ 1) * KV_STG_B);
            const size_t ko = (size_t)(kb + 1) * 64 * HSD;
            #pragma unroll
            for (int i = 0; i < 8; i++) CPASYNC(kvdst[i] + so, kvsrc[i] + ko);
            CP_COMMIT();
            CP_WAIT1();
        } else {
            CP_WAIT0();
        }
        __syncthreads();

        const uint32_t stg = sb + (uint32_t)(s * KV_STG_B);

        // ---- S = Q K^T
        float sf[8][4];
        #pragma unroll
        for (int jf = 0; jf < 8; jf++)
            #pragma unroll
            for (int e = 0; e < 4; e++) sf[jf][e] = 0.f;

        const uint32_t kBase = stg + pbOff;
        #pragma unroll
        for (int kk = 0; kk < 4; kk++)
            #pragma unroll
            for (int jp = 0; jp < 4; jp++) {
                uint32_t kh4[4], kl4[4];
                LDSM4(kh4, kBase + jp * (16 * AT_RS2) + kk * 32);
                LDSM4(kl4, kBase + KV_ARR_B + jp * (16 * AT_RS2) + kk * 32);
                MMA16816(sf[2 * jp],     qh[kk], &kh4[0]);
                MMA16816(sf[2 * jp],     qh[kk], &kl4[0]);
                MMA16816(sf[2 * jp],     ql[kk], &kh4[0]);
                MMA16816(sf[2 * jp + 1], qh[kk], &kh4[2]);
                MMA16816(sf[2 * jp + 1], qh[kk], &kl4[2]);
                MMA16816(sf[2 * jp + 1], ql[kk], &kh4[2]);
            }

        // ---- scale + causal mask
        const int k0 = kb * 64;
        const bool diag = (k0 + 63 > q0);
        #pragma unroll
        for (int jf = 0; jf < 8; jf++) {
            const int cb = k0 + 8 * jf + 2 * tq;
            sf[jf][0] *= 0.125f; sf[jf][1] *= 0.125f;
            sf[jf][2] *= 0.125f; sf[jf][3] *= 0.125f;
            if (diag) {
                if (cb     > row0) sf[jf][0] = -1e30f;
                if (cb + 1 > row0) sf[jf][1] = -1e30f;
                if (cb     > row1) sf[jf][2] = -1e30f;
                if (cb + 1 > row1) sf[jf][3] = -1e30f;
            }
        }

        // ---- online softmax
        float mx0 = -1e30f, mx1 = -1e30f;
        #pragma unroll
        for (int jf = 0; jf < 8; jf++) {
            mx0 = fmaxf(mx0, fmaxf(sf[jf][0], sf[jf][1]));
            mx1 = fmaxf(mx1, fmaxf(sf[jf][2], sf[jf][3]));
        }
        mx0 = fmaxf(mx0, __shfl_xor_sync(0xffffffffu, mx0, 1));
        mx0 = fmaxf(mx0, __shfl_xor_sync(0xffffffffu, mx0, 2));
        mx1 = fmaxf(mx1, __shfl_xor_sync(0xffffffffu, mx1, 1));
        mx1 = fmaxf(mx1, __shfl_xor_sync(0xffffffffu, mx1, 2));
        const float mn0 = fmaxf(m0, mx0), mn1 = fmaxf(m1, mx1);
        const float al0 = __expf(m0 - mn0), al1 = __expf(m1 - mn1);
        float rs0 = 0.f, rs1 = 0.f;
        #pragma unroll
        for (int jf = 0; jf < 8; jf++) {
            sf[jf][0] = __expf(sf[jf][0] - mn0);
            sf[jf][1] = __expf(sf[jf][1] - mn0);
            sf[jf][2] = __expf(sf[jf][2] - mn1);
            sf[jf][3] = __expf(sf[jf][3] - mn1);
            rs0 += sf[jf][0] + sf[jf][1];
            rs1 += sf[jf][2] + sf[jf][3];
        }
        rs0 += __shfl_xor_sync(0xffffffffu, rs0, 1);
        rs0 += __shfl_xor_sync(0xffffffffu, rs0, 2);
        rs1 += __shfl_xor_sync(0xffffffffu, rs1, 1);
        rs1 += __shfl_xor_sync(0xffffffffu, rs1, 2);
        l0 = l0 * al0 + rs0; l1 = l1 * al1 + rs1;
        m0 = mn0; m1 = mn1;
        #pragma unroll
        for (int df = 0; df < 8; df++) {
            acc[df][0] *= al0; acc[df][1] *= al0;
            acc[df][2] *= al1; acc[df][3] *= al1;
        }

        // ---- O += P V
        const uint32_t vBase = stg + 2 * KV_ARR_B + paOff;
        #pragma unroll
        for (int jp = 0; jp < 4; jp++) {
            uint32_t ah4[4], al4[4];
            split2(sf[2 * jp][0],     sf[2 * jp][1],     ah4[0], al4[0]);
            split2(sf[2 * jp][2],     sf[2 * jp][3],     ah4[1], al4[1]);
            split2(sf[2 * jp + 1][0], sf[2 * jp + 1][1], ah4[2], al4[2]);
            split2(sf[2 * jp + 1][2], sf[2 * jp + 1][3], ah4[3], al4[3]);
            #pragma unroll
            for (int dp = 0; dp < 4; dp++) {
                uint32_t vh4[4], vl4[4];
                LDSM4T(vh4, vBase + jp * (16 * AT_RS2) + dp * 32);
                LDSM4T(vl4, vBase + KV_ARR_B + jp * (16 * AT_RS2) + dp * 32);
                MMA16816(acc[2 * dp],     ah4, &vh4[0]);
                MMA16816(acc[2 * dp],     ah4, &vl4[0]);
                MMA16816(acc[2 * dp],     al4, &vh4[0]);
                MMA16816(acc[2 * dp + 1], ah4, &vh4[2]);
                MMA16816(acc[2 * dp + 1], ah4, &vl4[2]);
                MMA16816(acc[2 * dp + 1], al4, &vh4[2]);
            }
        }
        __syncthreads();
    }

    // ---- epilogue: y as bf16 hi/lo, layout [b][t][C]
    const int b = bh >> 4, h = bh & 15;
    const float i0 = 1.f / l0, i1 = 1.f / l1;
    #pragma unroll
    for (int df = 0; df < 8; df++) {
        const int col = h * HSD + 8 * df + 2 * tq;
        uint32_t hh, ll;
        split2(acc[df][0] * i0, acc[df][1] * i0, hh, ll);
        const size_t idx0 = ((size_t)(b * TLEN + row0)) * CDIM + col;
        *(uint32_t*)(yhg + idx0) = hh; *(uint32_t*)(ylg + idx0) = ll;
        split2(acc[df][2] * i1, acc[df][3] * i1, hh, ll);
        const size_t idx1 = ((size_t)(b * TLEN + row1)) * CDIM + col;
        *(uint32_t*)(yhg + idx1) = hh; *(uint32_t*)(ylg + idx1) = ll;
    }
}

// ---------------------------------------------------------------------------
extern "C" void kernel_launch(void* const* d_in, const int* in_sizes, int n_in,
                              void* d_out, int out_size) {
    const float* x  = (const float*)d_in[0];
    const float* Wq = (const float*)d_in[1];
    const float* bq = (const float*)d_in[2];
    const float* Wk = (const float*)d_in[3];
    const float* bk = (const float*)d_in[4];
    const float* Wv = (const float*)d_in[5];
    const float* bv = (const float*)d_in[6];
    const float* Wp = (const float*)d_in[7];
    const float* bp = (const float*)d_in[8];
    float* out = (float*)d_out;

    __nv_bfloat16 *xhi, *xlo, *whi, *wlo, *qhi, *qlo, *khi, *klo, *vhi, *vlo, *yhi, *ylo;
    cudaGetSymbolAddress((void**)&xhi, g_xhi);
    cudaGetSymbolAddress((void**)&xlo, g_xlo);
    cudaGetSymbolAddress((void**)&whi, g_whi);
    cudaGetSymbolAddress((void**)&wlo, g_wlo);
    cudaGetSymbolAddress((void**)&qhi, g_qhi);
    cudaGetSymbolAddress((void**)&qlo, g_qlo);
    cudaGetSymbolAddress((void**)&khi, g_khi);
    cudaGetSymbolAddress((void**)&klo, g_klo);
    cudaGetSymbolAddress((void**)&vhi, g_vhi);
    cudaGetSymbolAddress((void**)&vlo, g_vlo);
    cudaGetSymbolAddress((void**)&yhi, g_yhi);
    cudaGetSymbolAddress((void**)&ylo, g_ylo);

    static bool attr_set = false;
    if (!attr_set) {
        cudaFuncSetAttribute(attn_mma,
                             cudaFuncAttributeMaxDynamicSharedMemorySize, ATT_SMEM);
        cudaFuncSetAttribute(mma_gemm<0>,
                             cudaFuncAttributeMaxDynamicSharedMemorySize, GEMM_SMEM);
        cudaFuncSetAttribute(mma_gemm<1>,
                             cudaFuncAttributeMaxDynamicSharedMemorySize, GEMM_SMEM);
        attr_set = true;
    }

    const size_t WSZ = (size_t)CDIM * CDIM;

    split_kernel<<<MROWS*CDIM/1024, 256>>>(x, xhi, xlo, MROWS*CDIM);
    split_kernel<<<WSZ/1024, 256>>>(Wq, whi + 0*WSZ, wlo + 0*WSZ, (int)WSZ);
    split_kernel<<<WSZ/1024, 256>>>(Wk, whi + 1*WSZ, wlo + 1*WSZ, (int)WSZ);
    split_kernel<<<WSZ/1024, 256>>>(Wv, whi + 2*WSZ, wlo + 2*WSZ, (int)WSZ);
    split_kernel<<<WSZ/1024, 256>>>(Wp, whi + 3*WSZ, wlo + 3*WSZ, (int)WSZ);

    const dim3 gg(CDIM/128, MROWS/128);      // (8, 64)
    mma_gemm<1><<<gg, 256, GEMM_SMEM>>>(xhi, xlo, whi + 0*WSZ, wlo + 0*WSZ, bq,
                                        nullptr, qhi, qlo);
    mma_gemm<1><<<gg, 256, GEMM_SMEM>>>(xhi, xlo, whi + 1*WSZ, wlo + 1*WSZ, bk,
                                        nullptr, khi, klo);
    mma_gemm<1><<<gg, 256, GEMM_SMEM>>>(xhi, xlo, whi + 2*WSZ, wlo + 2*WSZ, bv,
                                        nullptr, vhi, vlo);

    attn_mma<<<dim3(TLEN/128, BATCH*NHEAD), 256, ATT_SMEM>>>(qhi, qlo, khi, klo,
                                                             vhi, vlo, yhi, ylo);

    mma_gemm<0><<<gg, 256, GEMM_SMEM>>>(yhi, ylo, whi + 3*WSZ, wlo + 3*WSZ, bp,
                                        out, nullptr, nullptr);
}